// round 13
// baseline (speedup 1.0000x reference)
#include <cuda_runtime.h>
#include <cuda.h>
#include <cstdint>
#include <cstddef>

#define HID  4096
#define INT_ 16384
#define MT   4096
#define NGU  32768

__device__ uint8_t g_xq [(size_t)MT  * HID];
__device__ float   g_xs [MT];
__device__ uint8_t g_wq [(size_t)NGU * HID];
__device__ float   g_ws [NGU];
__device__ uint8_t g_wdq[(size_t)HID * INT_];
__device__ float   g_wds[HID];
__device__ float   g_h  [(size_t)MT * INT_];
__device__ uint8_t g_hq [(size_t)MT * INT_];
__device__ float   g_hs [MT];

__device__ __forceinline__ uint32_t smem_u32(const void* p) {
    uint32_t a;
    asm("{ .reg .u64 t; cvta.to.shared.u64 t, %1; cvt.u32.u64 %0, t; }" : "=r"(a) : "l"(p));
    return a;
}
__device__ __forceinline__ uint32_t elect_one() {
    uint32_t p;
    asm volatile("{ .reg .pred p; elect.sync _|p, 0xFFFFFFFF; selp.b32 %0, 1, 0, p; }" : "=r"(p));
    return p;
}
#define MBARRIER_INIT(mb, c) \
    asm volatile("mbarrier.init.shared.b64 [%0], %1;" :: "r"((uint32_t)(mb)), "r"((uint32_t)(c)) : "memory")
#define MBARRIER_EXPECT_TX(mb, n) \
    asm volatile("mbarrier.arrive.expect_tx.shared.b64 _, [%0], %1;" \
                 :: "r"((uint32_t)(mb)), "r"((uint32_t)(n)) : "memory")
#define MBARRIER_ARRIVE(mb) \
    asm volatile("mbarrier.arrive.shared.b64 _, [%0];" :: "r"((uint32_t)(mb)) : "memory")
#define MBARRIER_WAIT(mb, ph) do {                                                    \
    uint32_t _m = (uint32_t)(mb); uint32_t _p = (uint32_t)(ph); uint32_t _d;           \
    asm volatile("{\n\t.reg .pred p;\n\t"                                              \
        "mbarrier.try_wait.parity.acquire.cta.shared::cta.b64 p, [%1], %2;\n\t"        \
        "selp.b32 %0, 1, 0, p;\n\t}" : "=r"(_d) : "r"(_m), "r"(_p) : "memory");        \
    if (!_d) {                                                                         \
        asm volatile("{\n\t.reg .pred P1;\n\t"                                         \
            "WL_%=:\n\t"                                                               \
            "mbarrier.try_wait.parity.acquire.cta.shared::cta.b64 P1, [%0], %1, 0x989680;\n\t" \
            "@P1 bra.uni WD_%=;\n\t"                                                   \
            "bra.uni WL_%=;\n\t"                                                       \
            "WD_%=:\n\t}" :: "r"(_m), "r"(_p) : "memory");                             \
    }                                                                                  \
} while (0)
#define TMA2D(sm, map, cx, cy, mb) \
    asm volatile("cp.async.bulk.tensor.2d.shared::cta.global.tile.mbarrier::complete_tx::bytes " \
                 "[%0], [%1, {%2, %3}], [%4];" \
                 :: "r"((uint32_t)(sm)), "l"(map), "r"((int)(cx)), "r"((int)(cy)), \
                    "r"((uint32_t)(mb)) : "memory")
#define LDS32(r, a) asm volatile("ld.shared.b32 %0, [%1];" : "=r"(r) : "r"(a))
#define IMMA(c, a, b0_, b1_) \
    asm volatile("mma.sync.aligned.m16n8k32.row.col.s32.s8.s8.s32 " \
        "{%0,%1,%2,%3}, {%4,%5,%6,%7}, {%8,%9}, {%0,%1,%2,%3};" \
        : "+r"((c)[0]), "+r"((c)[1]), "+r"((c)[2]), "+r"((c)[3]) \
        : "r"((a)[0]), "r"((a)[1]), "r"((a)[2]), "r"((a)[3]), "r"(b0_), "r"(b1_))

// XLA GPU tanh (rational approx) -> logistic via 0.5*tanh(0.5x)+0.5
__device__ __forceinline__ float tanh_xla(float x) {
    if (fabsf(x) < 0.0004f) return x;
    float xc = fminf(fmaxf(x, -7.90531110763549805f), 7.90531110763549805f);
    float x2 = xc * xc;
    float p = fmaf(x2, -2.76076847742355e-16f, 2.00018790482477e-13f);
    p = fmaf(x2, p, -8.60467152213735e-11f);
    p = fmaf(x2, p, 5.12229709037114e-08f);
    p = fmaf(x2, p, 1.48572235717979e-05f);
    p = fmaf(x2, p, 6.37261928875436e-04f);
    p = fmaf(x2, p, 4.89352455891786e-03f);
    p = xc * p;
    float q = fmaf(x2, 1.19825839466702e-06f, 1.18534705686654e-04f);
    q = fmaf(x2, q, 2.26843463243900e-03f);
    q = fmaf(x2, q, 4.89352518554385e-03f);
    return __fdiv_rn(p, q);
}
__device__ __forceinline__ float silu_xla(float g, float u) {
    float sig = fmaf(0.5f, tanh_xla(0.5f * g), 0.5f);
    return (g * sig) * u;
}
__device__ __forceinline__ int q_fast(float x, float inv) {
    int qi = __float2int_rn(x * inv);
    return max(-8, min(7, qi));
}
__device__ __forceinline__ uint32_t pack4i(float a, float b, float c, float d, float inv) {
    int q0 = q_fast(a, inv), q1 = q_fast(b, inv);
    int q2 = q_fast(c, inv), q3 = q_fast(d, inv);
    return (uint32_t)(q0 & 255) | ((uint32_t)(q1 & 255) << 8) |
           ((uint32_t)(q2 & 255) << 16) | ((uint32_t)(q3 & 255) << 24);
}
// HYPOTHESIS UNDER TEST: scale = max * RN(1/7)  (XLA div->recip-mul rewrite)
__device__ __forceinline__ float mk_scale(float mx) {
    return fmaxf(mx * (1.0f / 7.0f), 1e-8f);
}

template <int VPT>
__global__ void __launch_bounds__(256)
quant_rows(const float* __restrict__ X, uint8_t* __restrict__ Q,
           float* __restrict__ S, int K) {
    __shared__ float red[8];
    int row = blockIdx.x, t = threadIdx.x;
    const float4* src = (const float4*)(X + (size_t)row * K);
    float4 v[VPT];
    float mx = 0.f;
#pragma unroll
    for (int i = 0; i < VPT; i++) {
        v[i] = src[t + i * 256];
        mx = fmaxf(mx, fmaxf(fmaxf(fabsf(v[i].x), fabsf(v[i].y)),
                             fmaxf(fabsf(v[i].z), fabsf(v[i].w))));
    }
#pragma unroll
    for (int o = 16; o; o >>= 1) mx = fmaxf(mx, __shfl_xor_sync(~0u, mx, o));
    if ((t & 31) == 0) red[t >> 5] = mx;
    __syncthreads();
    if (t < 32) {
        float m2 = (t < 8) ? red[t] : 0.f;
#pragma unroll
        for (int o = 4; o; o >>= 1) m2 = fmaxf(m2, __shfl_xor_sync(~0u, m2, o));
        if (t == 0) red[0] = m2;
    }
    __syncthreads();
    float s = mk_scale(red[0]);
    float inv = __frcp_rn(s);
    if (t == 0) S[row] = s;
    uint32_t* dst = (uint32_t*)(Q + (size_t)row * K);
#pragma unroll
    for (int i = 0; i < VPT; i++)
        dst[t + i * 256] = pack4i(v[i].x, v[i].y, v[i].z, v[i].w, inv);
}

template <bool SILU>
__global__ void __launch_bounds__(256, 1)
gemm_dual(const __grid_constant__ CUtensorMap tmA,
          const __grid_constant__ CUtensorMap tmB,
          const float* __restrict__ sA, const float* __restrict__ sB,
          float* __restrict__ OUT, int K, int ldo) {
    extern __shared__ uint8_t dynraw[];
    __shared__ __align__(8) uint64_t barr[8];
    __shared__ float sB_sm[2][128];
    __shared__ float sA_sm[128];

    const int tid = threadIdx.x, wid = tid >> 5, lid = tid & 31;
    const int m0 = blockIdx.x * 128;
    const int r0 = SILU ? blockIdx.y * 128 : blockIdx.y * 256;
    const int r1 = SILU ? (INT_ + r0) : (r0 + 128);
    const int c0 = r0;
    const int NC = K >> 7;

    const uint32_t dynb = (smem_u32(dynraw) + 1023) & ~1023u;
    const uint32_t mbF = smem_u32(barr), mbE = mbF + 32;

    if (tid == 0)
        for (int s = 0; s < 4; s++) { MBARRIER_INIT(mbF + 8 * s, 1); MBARRIER_INIT(mbE + 8 * s, 256); }
    if (tid < 128) {
        sB_sm[0][tid] = sB[r0 + tid];
        sB_sm[1][tid] = sB[r1 + tid];
        sA_sm[tid]    = sA[m0 + tid];
    }
    __syncthreads();

    const int g   = lid >> 2;
    const int t4  = (lid & 3) * 4;
    const int m0w = (wid >> 2) * 64;
    const int n0w = (wid & 3) * 32;

    int acc[2][4][4][4];
#pragma unroll
    for (int a = 0; a < 2; a++)
#pragma unroll
        for (int b = 0; b < 4; b++)
#pragma unroll
            for (int c = 0; c < 4; c++)
#pragma unroll
                for (int d = 0; d < 4; d++) acc[a][b][c][d] = 0;

    const bool prod = (wid == 0) && elect_one();
    auto issue = [&](int nx) {
        uint32_t s = nx & 3;
        if (nx >= 4) MBARRIER_WAIT(mbE + 8 * s, ((nx - 4) >> 2) & 1);
        uint32_t stg = dynb + s * 49152;
        MBARRIER_EXPECT_TX(mbF + 8 * s, 49152);
        TMA2D(stg,         &tmA, nx * 128, m0, mbF + 8 * s);
        TMA2D(stg + 16384, &tmB, nx * 128, r0, mbF + 8 * s);
        TMA2D(stg + 32768, &tmB, nx * 128, r1, mbF + 8 * s);
    };
    if (prod) { issue(0); issue(1); issue(2); }

    for (int cc = 0; cc < NC; cc++) {
        if (prod && cc + 3 < NC) issue(cc + 3);
        uint32_t s = cc & 3;
        MBARRIER_WAIT(mbF + 8 * s, (cc >> 2) & 1);
        uint32_t stg = dynb + s * 49152;
#pragma unroll
        for (int ks = 0; ks < 4; ks++) {
            const int kb = ks * 32 + t4;
            uint32_t a[4][4];
#pragma unroll
            for (int mf = 0; mf < 4; mf++) {
                int r = m0w + mf * 16 + g;
                uint32_t rb = stg + r * 128;
                uint32_t sw = (r & 7) << 4;
                LDS32(a[mf][0], rb +        ( kb       ^ sw));
                LDS32(a[mf][1], rb + 1024 + ( kb       ^ sw));
                LDS32(a[mf][2], rb +        ((kb + 16) ^ sw));
                LDS32(a[mf][3], rb + 1024 + ((kb + 16) ^ sw));
            }
#pragma unroll
            for (int tl = 0; tl < 2; tl++) {
                uint32_t bst = stg + 16384 + tl * 16384;
#pragma unroll
                for (int nf = 0; nf < 4; nf++) {
                    int rn = n0w + nf * 8 + g;
                    uint32_t rb = bst + rn * 128;
                    uint32_t sw = (rn & 7) << 4;
                    uint32_t b0, b1;
                    LDS32(b0, rb + ( kb       ^ sw));
                    LDS32(b1, rb + ((kb + 16) ^ sw));
#pragma unroll
                    for (int mf = 0; mf < 4; mf++)
                        IMMA(acc[tl][mf][nf], a[mf], b0, b1);
                }
            }
        }
        MBARRIER_ARRIVE(mbE + 8 * s);
    }

    const int t2 = (lid & 3) * 2;
#pragma unroll
    for (int mf = 0; mf < 4; mf++) {
        int rl = m0w + mf * 16 + g;
        float sa0 = sA_sm[rl], sa1 = sA_sm[rl + 8];
        float* o0 = OUT + (size_t)(m0 + rl)     * ldo + c0;
        float* o1 = OUT + (size_t)(m0 + rl + 8) * ldo + c0;
#pragma unroll
        for (int nf = 0; nf < 4; nf++) {
            int cl = n0w + nf * 8 + t2;
            float s00 = sB_sm[0][cl], s01 = sB_sm[0][cl + 1];
            float s10 = sB_sm[1][cl], s11 = sB_sm[1][cl + 1];
            const int* cg = acc[0][mf][nf];
            const int* cu = acc[1][mf][nf];
            if (SILU) {
                float gg[4] = {(float)cg[0] * sa0 * s00, (float)cg[1] * sa0 * s01,
                               (float)cg[2] * sa1 * s00, (float)cg[3] * sa1 * s01};
                float uu[4] = {(float)cu[0] * sa0 * s10, (float)cu[1] * sa0 * s11,
                               (float)cu[2] * sa1 * s10, (float)cu[3] * sa1 * s11};
                float hh[4];
#pragma unroll
                for (int q = 0; q < 4; q++) hh[q] = silu_xla(gg[q], uu[q]);
                *(float2*)(o0 + cl) = make_float2(hh[0], hh[1]);
                *(float2*)(o1 + cl) = make_float2(hh[2], hh[3]);
            } else {
                *(float2*)(o0 + cl)       = make_float2((float)cg[0] * sa0 * s00,
                                                        (float)cg[1] * sa0 * s01);
                *(float2*)(o1 + cl)       = make_float2((float)cg[2] * sa1 * s00,
                                                        (float)cg[3] * sa1 * s01);
                *(float2*)(o0 + 128 + cl) = make_float2((float)cu[0] * sa0 * s10,
                                                        (float)cu[1] * sa0 * s11);
                *(float2*)(o1 + 128 + cl) = make_float2((float)cu[2] * sa1 * s10,
                                                        (float)cu[3] * sa1 * s11);
            }
        }
    }
}

__global__ void __launch_bounds__(512)
fwht_quant(const float* __restrict__ H, uint8_t* __restrict__ Q, float* __restrict__ S) {
    extern __shared__ float sh[];
    __shared__ float red[16];
    int row = blockIdx.x, t = threadIdx.x;
    const float4* src = (const float4*)(H + (size_t)row * INT_);
#pragma unroll
    for (int i = 0; i < 8; i++) {
        float4 v = src[t + i * 512];
        int b = (t + i * 512) * 4;
        sh[b] = v.x; sh[b + 1] = v.y; sh[b + 2] = v.z; sh[b + 3] = v.w;
    }
    __syncthreads();
    for (int hh = 1; hh < INT_; hh <<= 1) {
        for (int idx = t; idx < INT_ / 2; idx += 512) {
            int i = ((idx & ~(hh - 1)) << 1) | (idx & (hh - 1));
            float a = sh[i], b = sh[i + hh];
            sh[i] = a + b;
            sh[i + hh] = a - b;
        }
        __syncthreads();
    }
    float mx = 0.f;
    for (int i = t; i < INT_; i += 512) {
        float v = sh[i] * 0.0078125f;
        sh[i] = v;
        mx = fmaxf(mx, fabsf(v));
    }
#pragma unroll
    for (int o = 16; o; o >>= 1) mx = fmaxf(mx, __shfl_xor_sync(~0u, mx, o));
    if ((t & 31) == 0) red[t >> 5] = mx;
    __syncthreads();
    if (t < 32) {
        float m2 = (t < 16) ? red[t] : 0.f;
#pragma unroll
        for (int o = 8; o; o >>= 1) m2 = fmaxf(m2, __shfl_xor_sync(~0u, m2, o));
        if (t == 0) red[0] = m2;
    }
    __syncthreads();
    float s = mk_scale(red[0]);
    float inv = __frcp_rn(s);
    if (t == 0) S[row] = s;
    uint32_t* dst = (uint32_t*)(Q + (size_t)row * INT_);
    for (int i = t; i < INT_ / 4; i += 512)
        dst[i] = pack4i(sh[4 * i], sh[4 * i + 1], sh[4 * i + 2], sh[4 * i + 3], inv);
}

typedef CUresult (*EncFn)(CUtensorMap*, CUtensorMapDataType, cuuint32_t, void*,
                          const cuuint64_t*, const cuuint64_t*, const cuuint32_t*,
                          const cuuint32_t*, CUtensorMapInterleave, CUtensorMapSwizzle,
                          CUtensorMapL2promotion, CUtensorMapFloatOOBfill);

static void enc_map(EncFn f, CUtensorMap* m, void* p, uint64_t d0, uint64_t d1) {
    cuuint64_t dims[2] = {d0, d1};
    cuuint64_t str[1]  = {d0};
    cuuint32_t box[2]  = {128u, 128u};
    cuuint32_t es[2]   = {1u, 1u};
    f(m, CU_TENSOR_MAP_DATA_TYPE_UINT8, 2, p, dims, str, box, es,
      CU_TENSOR_MAP_INTERLEAVE_NONE, CU_TENSOR_MAP_SWIZZLE_128B,
      CU_TENSOR_MAP_L2_PROMOTION_L2_128B, CU_TENSOR_MAP_FLOAT_OOB_FILL_NONE);
}

extern "C" void kernel_launch(void* const* d_in, const int* in_sizes, int n_in,
                              void* d_out, int out_size) {
    void *xq, *wq, *wdq, *hq, *xs, *ws, *wds, *h, *hs;
    cudaGetSymbolAddress(&xq,  g_xq);
    cudaGetSymbolAddress(&xs,  g_xs);
    cudaGetSymbolAddress(&wq,  g_wq);
    cudaGetSymbolAddress(&ws,  g_ws);
    cudaGetSymbolAddress(&wdq, g_wdq);
    cudaGetSymbolAddress(&wds, g_wds);
    cudaGetSymbolAddress(&h,   g_h);
    cudaGetSymbolAddress(&hq,  g_hq);
    cudaGetSymbolAddress(&hs,  g_hs);

    EncFn f = nullptr;
    cudaDriverEntryPointQueryResult qr;
    cudaGetDriverEntryPoint("cuTensorMapEncodeTiled", (void**)&f, cudaEnableDefault, &qr);

    CUtensorMap tA1, tB1, tA2, tB2;
    enc_map(f, &tA1, xq,  HID,  MT);
    enc_map(f, &tB1, wq,  HID,  NGU);
    enc_map(f, &tA2, hq,  INT_, MT);
    enc_map(f, &tB2, wdq, INT_, HID);

    cudaFuncSetAttribute(gemm_dual<true>,  cudaFuncAttributeMaxDynamicSharedMemorySize, 197632);
    cudaFuncSetAttribute(gemm_dual<false>, cudaFuncAttributeMaxDynamicSharedMemorySize, 197632);
    cudaFuncSetAttribute(fwht_quant,       cudaFuncAttributeMaxDynamicSharedMemorySize, 65536);

    quant_rows<4><<<MT,  256>>>((const float*)d_in[0], (uint8_t*)xq,  (float*)xs,  HID);
    quant_rows<4><<<NGU, 256>>>((const float*)d_in[1], (uint8_t*)wq,  (float*)ws,  HID);
    quant_rows<16><<<HID, 256>>>((const float*)d_in[2], (uint8_t*)wdq, (float*)wds, INT_);

    gemm_dual<true><<<dim3(32, 128), 256, 197632>>>(
        tA1, tB1, (const float*)xs, (const float*)ws, (float*)h, HID, INT_);

    fwht_quant<<<MT, 512, 65536>>>((const float*)h, (uint8_t*)hq, (float*)hs);

    gemm_dual<false><<<dim3(32, 16), 256, 197632>>>(
        tA2, tB2, (const float*)hs, (const float*)wds, (float*)d_out, INT_, HID);
}

// round 14
// speedup vs baseline: 1.0604x; 1.0604x over previous
#include <cuda_runtime.h>
#include <cuda.h>
#include <cstdint>
#include <cstddef>

#define HID  4096
#define INT_ 16384
#define MT   4096
#define NGU  32768

__device__ uint8_t g_xq [(size_t)MT  * HID];
__device__ float   g_xs [MT];
__device__ uint8_t g_wq [(size_t)NGU * HID];
__device__ float   g_ws [NGU];
__device__ uint8_t g_wdq[(size_t)HID * INT_];
__device__ float   g_wds[HID];
__device__ float   g_h  [(size_t)MT * INT_];
__device__ uint8_t g_hq [(size_t)MT * INT_];
__device__ float   g_hs [MT];

__device__ __forceinline__ uint32_t smem_u32(const void* p) {
    uint32_t a;
    asm("{ .reg .u64 t; cvta.to.shared.u64 t, %1; cvt.u32.u64 %0, t; }" : "=r"(a) : "l"(p));
    return a;
}
__device__ __forceinline__ uint32_t elect_one() {
    uint32_t p;
    asm volatile("{ .reg .pred p; elect.sync _|p, 0xFFFFFFFF; selp.b32 %0, 1, 0, p; }" : "=r"(p));
    return p;
}
#define MBARRIER_INIT(mb, c) \
    asm volatile("mbarrier.init.shared.b64 [%0], %1;" :: "r"((uint32_t)(mb)), "r"((uint32_t)(c)) : "memory")
#define MBARRIER_EXPECT_TX(mb, n) \
    asm volatile("mbarrier.arrive.expect_tx.shared.b64 _, [%0], %1;" \
                 :: "r"((uint32_t)(mb)), "r"((uint32_t)(n)) : "memory")
#define MBARRIER_ARRIVE(mb) \
    asm volatile("mbarrier.arrive.shared.b64 _, [%0];" :: "r"((uint32_t)(mb)) : "memory")
#define MBARRIER_WAIT(mb, ph) do {                                                    \
    uint32_t _m = (uint32_t)(mb); uint32_t _p = (uint32_t)(ph); uint32_t _d;           \
    asm volatile("{\n\t.reg .pred p;\n\t"                                              \
        "mbarrier.try_wait.parity.acquire.cta.shared::cta.b64 p, [%1], %2;\n\t"        \
        "selp.b32 %0, 1, 0, p;\n\t}" : "=r"(_d) : "r"(_m), "r"(_p) : "memory");        \
    if (!_d) {                                                                         \
        asm volatile("{\n\t.reg .pred P1;\n\t"                                         \
            "WL_%=:\n\t"                                                               \
            "mbarrier.try_wait.parity.acquire.cta.shared::cta.b64 P1, [%0], %1, 0x989680;\n\t" \
            "@P1 bra.uni WD_%=;\n\t"                                                   \
            "bra.uni WL_%=;\n\t"                                                       \
            "WD_%=:\n\t}" :: "r"(_m), "r"(_p) : "memory");                             \
    }                                                                                  \
} while (0)
#define TMA2D(sm, map, cx, cy, mb) \
    asm volatile("cp.async.bulk.tensor.2d.shared::cta.global.tile.mbarrier::complete_tx::bytes " \
                 "[%0], [%1, {%2, %3}], [%4];" \
                 :: "r"((uint32_t)(sm)), "l"(map), "r"((int)(cx)), "r"((int)(cy)), \
                    "r"((uint32_t)(mb)) : "memory")
#define LDS32(r, a) asm volatile("ld.shared.b32 %0, [%1];" : "=r"(r) : "r"(a))
#define IMMA(c, a, b0_, b1_) \
    asm volatile("mma.sync.aligned.m16n8k32.row.col.s32.s8.s8.s32 " \
        "{%0,%1,%2,%3}, {%4,%5,%6,%7}, {%8,%9}, {%0,%1,%2,%3};" \
        : "+r"((c)[0]), "+r"((c)[1]), "+r"((c)[2]), "+r"((c)[3]) \
        : "r"((a)[0]), "r"((a)[1]), "r"((a)[2]), "r"((a)[3]), "r"(b0_), "r"(b1_))

__device__ __forceinline__ float tanh_xla(float x) {
    if (fabsf(x) < 0.0004f) return x;
    float xc = fminf(fmaxf(x, -7.90531110763549805f), 7.90531110763549805f);
    float x2 = xc * xc;
    float p = fmaf(x2, -2.76076847742355e-16f, 2.00018790482477e-13f);
    p = fmaf(x2, p, -8.60467152213735e-11f);
    p = fmaf(x2, p, 5.12229709037114e-08f);
    p = fmaf(x2, p, 1.48572235717979e-05f);
    p = fmaf(x2, p, 6.37261928875436e-04f);
    p = fmaf(x2, p, 4.89352455891786e-03f);
    p = xc * p;
    float q = fmaf(x2, 1.19825839466702e-06f, 1.18534705686654e-04f);
    q = fmaf(x2, q, 2.26843463243900e-03f);
    q = fmaf(x2, q, 4.89352518554385e-03f);
    return __fdiv_rn(p, q);
}
__device__ __forceinline__ float silu_xla(float g, float u) {
    float sig = fmaf(0.5f, tanh_xla(0.5f * g), 0.5f);
    return (g * sig) * u;
}
__device__ __forceinline__ int q_fast(float x, float inv) {
    int qi = __float2int_rn(x * inv);
    return max(-8, min(7, qi));
}
__device__ __forceinline__ uint32_t pack4i(float a, float b, float c, float d, float inv) {
    int q0 = q_fast(a, inv), q1 = q_fast(b, inv);
    int q2 = q_fast(c, inv), q3 = q_fast(d, inv);
    return (uint32_t)(q0 & 255) | ((uint32_t)(q1 & 255) << 8) |
           ((uint32_t)(q2 & 255) << 16) | ((uint32_t)(q3 & 255) << 24);
}
// matches reference-as-compiled: scale = max * RN(1/7)
__device__ __forceinline__ float mk_scale(float mx) {
    return fmaxf(mx * (1.0f / 7.0f), 1e-8f);
}

template <int VPT>
__global__ void __launch_bounds__(256)
quant_rows(const float* __restrict__ X, uint8_t* __restrict__ Q,
           float* __restrict__ S, int K) {
    __shared__ float red[8];
    int row = blockIdx.x, t = threadIdx.x;
    const float4* src = (const float4*)(X + (size_t)row * K);
    float4 v[VPT];
    float mx = 0.f;
#pragma unroll
    for (int i = 0; i < VPT; i++) {
        v[i] = src[t + i * 256];
        mx = fmaxf(mx, fmaxf(fmaxf(fabsf(v[i].x), fabsf(v[i].y)),
                             fmaxf(fabsf(v[i].z), fabsf(v[i].w))));
    }
#pragma unroll
    for (int o = 16; o; o >>= 1) mx = fmaxf(mx, __shfl_xor_sync(~0u, mx, o));
    if ((t & 31) == 0) red[t >> 5] = mx;
    __syncthreads();
    if (t < 32) {
        float m2 = (t < 8) ? red[t] : 0.f;
#pragma unroll
        for (int o = 4; o; o >>= 1) m2 = fmaxf(m2, __shfl_xor_sync(~0u, m2, o));
        if (t == 0) red[0] = m2;
    }
    __syncthreads();
    float s = mk_scale(red[0]);
    float inv = __frcp_rn(s);
    if (t == 0) S[row] = s;
    uint32_t* dst = (uint32_t*)(Q + (size_t)row * K);
#pragma unroll
    for (int i = 0; i < VPT; i++)
        dst[t + i * 256] = pack4i(v[i].x, v[i].y, v[i].z, v[i].w, inv);
}

// dual-tile s8 GEMM: even chunks on IMMA pipe, odd chunks mostly on dp4a (ALU) pipe.
template <bool SILU>
__global__ void __launch_bounds__(256, 1)
gemm_dual(const __grid_constant__ CUtensorMap tmA,
          const __grid_constant__ CUtensorMap tmB,
          const float* __restrict__ sA, const float* __restrict__ sB,
          float* __restrict__ OUT, int K, int ldo) {
    extern __shared__ uint8_t dynraw[];
    __shared__ __align__(8) uint64_t barr[8];
    __shared__ float sB_sm[2][128];
    __shared__ float sA_sm[128];

    const int tid = threadIdx.x, wid = tid >> 5, lid = tid & 31;
    const int m0 = blockIdx.x * 128;
    const int r0 = SILU ? blockIdx.y * 128 : blockIdx.y * 256;
    const int r1 = SILU ? (INT_ + r0) : (r0 + 128);
    const int c0 = r0;
    const int NC = K >> 7;

    const uint32_t dynb = (smem_u32(dynraw) + 1023) & ~1023u;
    const uint32_t mbF = smem_u32(barr), mbE = mbF + 32;

    if (tid == 0)
        for (int s = 0; s < 4; s++) { MBARRIER_INIT(mbF + 8 * s, 1); MBARRIER_INIT(mbE + 8 * s, 256); }
    if (tid < 128) {
        sB_sm[0][tid] = sB[r0 + tid];
        sB_sm[1][tid] = sB[r1 + tid];
        sA_sm[tid]    = sA[m0 + tid];
    }
    __syncthreads();

    const int g   = lid >> 2;
    const int t4  = (lid & 3) * 4;
    const int t2  = (lid & 3) * 2;
    const int m0w = (wid >> 2) * 64;
    const int n0w = (wid & 3) * 32;

    int acc[2][4][4][4];
#pragma unroll
    for (int a = 0; a < 2; a++)
#pragma unroll
        for (int b = 0; b < 4; b++)
#pragma unroll
            for (int c = 0; c < 4; c++)
#pragma unroll
                for (int d = 0; d < 4; d++) acc[a][b][c][d] = 0;

    const bool prod = (wid == 0) && elect_one();
    auto issue = [&](int nx) {
        uint32_t s = nx & 3;
        if (nx >= 4) MBARRIER_WAIT(mbE + 8 * s, ((nx - 4) >> 2) & 1);
        uint32_t stg = dynb + s * 49152;
        MBARRIER_EXPECT_TX(mbF + 8 * s, 49152);
        TMA2D(stg,         &tmA, nx * 128, m0, mbF + 8 * s);
        TMA2D(stg + 16384, &tmB, nx * 128, r0, mbF + 8 * s);
        TMA2D(stg + 32768, &tmB, nx * 128, r1, mbF + 8 * s);
    };
    if (prod) { issue(0); issue(1); issue(2); issue(3); }

    // one ks-block (k-slice of 32 bytes) via IMMA
    auto imma_ks = [&](uint32_t stg, int ks) {
        const int kb = ks * 32 + t4;
        uint32_t a[4][4];
#pragma unroll
        for (int mf = 0; mf < 4; mf++) {
            int r = m0w + mf * 16 + g;
            uint32_t rb = stg + r * 128;
            uint32_t sw = (r & 7) << 4;
            LDS32(a[mf][0], rb +        ( kb       ^ sw));
            LDS32(a[mf][1], rb + 1024 + ( kb       ^ sw));
            LDS32(a[mf][2], rb +        ((kb + 16) ^ sw));
            LDS32(a[mf][3], rb + 1024 + ((kb + 16) ^ sw));
        }
#pragma unroll
        for (int tl = 0; tl < 2; tl++) {
            uint32_t bst = stg + 16384 + tl * 16384;
#pragma unroll
            for (int nf = 0; nf < 4; nf++) {
                int rn = n0w + nf * 8 + g;
                uint32_t rb = bst + rn * 128;
                uint32_t sw = (rn & 7) << 4;
                uint32_t b0, b1;
                LDS32(b0, rb + ( kb       ^ sw));
                LDS32(b1, rb + ((kb + 16) ^ sw));
#pragma unroll
                for (int mf = 0; mf < 4; mf++)
                    IMMA(acc[tl][mf][nf], a[mf], b0, b1);
            }
        }
    };

    // one ks-block via dp4a into the same s32 accumulators (bit-identical)
    auto dp4a_ks = [&](uint32_t stg, int ks) {
#pragma unroll
        for (int w = 0; w < 8; w++) {
            const int kb4 = ks * 32 + w * 4;
            uint32_t av[8], bv[16];
#pragma unroll
            for (int mf = 0; mf < 4; mf++)
#pragma unroll
                for (int h2 = 0; h2 < 2; h2++) {
                    int r = m0w + mf * 16 + g + h2 * 8;
                    LDS32(av[mf * 2 + h2], stg + r * 128 + (kb4 ^ ((r & 7) << 4)));
                }
#pragma unroll
            for (int tl = 0; tl < 2; tl++)
#pragma unroll
                for (int nf = 0; nf < 4; nf++)
#pragma unroll
                    for (int c = 0; c < 2; c++) {
                        int rn = n0w + nf * 8 + t2 + c;
                        LDS32(bv[tl * 8 + nf * 2 + c],
                              stg + 16384 + tl * 16384 + rn * 128 + (kb4 ^ ((rn & 7) << 4)));
                    }
#pragma unroll
            for (int tl = 0; tl < 2; tl++)
#pragma unroll
                for (int mf = 0; mf < 4; mf++)
#pragma unroll
                    for (int nf = 0; nf < 4; nf++) {
                        acc[tl][mf][nf][0] = __dp4a((int)av[mf*2],   (int)bv[tl*8+nf*2],   acc[tl][mf][nf][0]);
                        acc[tl][mf][nf][1] = __dp4a((int)av[mf*2],   (int)bv[tl*8+nf*2+1], acc[tl][mf][nf][1]);
                        acc[tl][mf][nf][2] = __dp4a((int)av[mf*2+1], (int)bv[tl*8+nf*2],   acc[tl][mf][nf][2]);
                        acc[tl][mf][nf][3] = __dp4a((int)av[mf*2+1], (int)bv[tl*8+nf*2+1], acc[tl][mf][nf][3]);
                    }
        }
    };

    for (int it = 0; it < NC / 2; it++) {
        const int ci = 2 * it, cd = 2 * it + 1;
        const uint32_t s0 = ci & 3, s1 = cd & 3;
        MBARRIER_WAIT(mbF + 8 * s0, (ci >> 2) & 1);
        MBARRIER_WAIT(mbF + 8 * s1, (cd >> 2) & 1);
        const uint32_t stg0 = dynb + s0 * 49152;
        const uint32_t stg1 = dynb + s1 * 49152;
#pragma unroll
        for (int ks = 0; ks < 4; ks++) {
            imma_ks(stg0, ks);                 // tensor pipe
            if (ks < 3) dp4a_ks(stg1, ks);     // alu pipe (overlaps)
        }
        imma_ks(stg1, 3);                      // balance: last ks of odd chunk on IMMA
        MBARRIER_ARRIVE(mbE + 8 * s0);
        MBARRIER_ARRIVE(mbE + 8 * s1);
        if (prod) {
            if (ci + 4 < NC) issue(ci + 4);
            if (cd + 4 < NC) issue(cd + 4);
        }
    }

    // epilogue (unchanged)
#pragma unroll
    for (int mf = 0; mf < 4; mf++) {
        int rl = m0w + mf * 16 + g;
        float sa0 = sA_sm[rl], sa1 = sA_sm[rl + 8];
        float* o0 = OUT + (size_t)(m0 + rl)     * ldo + c0;
        float* o1 = OUT + (size_t)(m0 + rl + 8) * ldo + c0;
#pragma unroll
        for (int nf = 0; nf < 4; nf++) {
            int cl = n0w + nf * 8 + t2;
            float s00 = sB_sm[0][cl], s01 = sB_sm[0][cl + 1];
            float s10 = sB_sm[1][cl], s11 = sB_sm[1][cl + 1];
            const int* cg = acc[0][mf][nf];
            const int* cu = acc[1][mf][nf];
            if (SILU) {
                float gg[4] = {(float)cg[0] * sa0 * s00, (float)cg[1] * sa0 * s01,
                               (float)cg[2] * sa1 * s00, (float)cg[3] * sa1 * s01};
                float uu[4] = {(float)cu[0] * sa0 * s10, (float)cu[1] * sa0 * s11,
                               (float)cu[2] * sa1 * s10, (float)cu[3] * sa1 * s11};
                float hh[4];
#pragma unroll
                for (int q = 0; q < 4; q++) hh[q] = silu_xla(gg[q], uu[q]);
                *(float2*)(o0 + cl) = make_float2(hh[0], hh[1]);
                *(float2*)(o1 + cl) = make_float2(hh[2], hh[3]);
            } else {
                *(float2*)(o0 + cl)       = make_float2((float)cg[0] * sa0 * s00,
                                                        (float)cg[1] * sa0 * s01);
                *(float2*)(o1 + cl)       = make_float2((float)cg[2] * sa1 * s00,
                                                        (float)cg[3] * sa1 * s01);
                *(float2*)(o0 + 128 + cl) = make_float2((float)cu[0] * sa0 * s10,
                                                        (float)cu[1] * sa0 * s11);
                *(float2*)(o1 + 128 + cl) = make_float2((float)cu[2] * sa1 * s10,
                                                        (float)cu[3] * sa1 * s11);
            }
        }
    }
}

__global__ void __launch_bounds__(512)
fwht_quant(const float* __restrict__ H, uint8_t* __restrict__ Q, float* __restrict__ S) {
    extern __shared__ float sh[];
    __shared__ float red[16];
    int row = blockIdx.x, t = threadIdx.x;
    const float4* src = (const float4*)(H + (size_t)row * INT_);
#pragma unroll
    for (int i = 0; i < 8; i++) {
        float4 v = src[t + i * 512];
        int b = (t + i * 512) * 4;
        sh[b] = v.x; sh[b + 1] = v.y; sh[b + 2] = v.z; sh[b + 3] = v.w;
    }
    __syncthreads();
    for (int hh = 1; hh < INT_; hh <<= 1) {
        for (int idx = t; idx < INT_ / 2; idx += 512) {
            int i = ((idx & ~(hh - 1)) << 1) | (idx & (hh - 1));
            float a = sh[i], b = sh[i + hh];
            sh[i] = a + b;
            sh[i + hh] = a - b;
        }
        __syncthreads();
    }
    float mx = 0.f;
    for (int i = t; i < INT_; i += 512) {
        float v = sh[i] * 0.0078125f;
        sh[i] = v;
        mx = fmaxf(mx, fabsf(v));
    }
#pragma unroll
    for (int o = 16; o; o >>= 1) mx = fmaxf(mx, __shfl_xor_sync(~0u, mx, o));
    if ((t & 31) == 0) red[t >> 5] = mx;
    __syncthreads();
    if (t < 32) {
        float m2 = (t < 16) ? red[t] : 0.f;
#pragma unroll
        for (int o = 8; o; o >>= 1) m2 = fmaxf(m2, __shfl_xor_sync(~0u, m2, o));
        if (t == 0) red[0] = m2;
    }
    __syncthreads();
    float s = mk_scale(red[0]);
    float inv = __frcp_rn(s);
    if (t == 0) S[row] = s;
    uint32_t* dst = (uint32_t*)(Q + (size_t)row * INT_);
    for (int i = t; i < INT_ / 4; i += 512)
        dst[i] = pack4i(sh[4 * i], sh[4 * i + 1], sh[4 * i + 2], sh[4 * i + 3], inv);
}

typedef CUresult (*EncFn)(CUtensorMap*, CUtensorMapDataType, cuuint32_t, void*,
                          const cuuint64_t*, const cuuint64_t*, const cuuint32_t*,
                          const cuuint32_t*, CUtensorMapInterleave, CUtensorMapSwizzle,
                          CUtensorMapL2promotion, CUtensorMapFloatOOBfill);

static void enc_map(EncFn f, CUtensorMap* m, void* p, uint64_t d0, uint64_t d1) {
    cuuint64_t dims[2] = {d0, d1};
    cuuint64_t str[1]  = {d0};
    cuuint32_t box[2]  = {128u, 128u};
    cuuint32_t es[2]   = {1u, 1u};
    f(m, CU_TENSOR_MAP_DATA_TYPE_UINT8, 2, p, dims, str, box, es,
      CU_TENSOR_MAP_INTERLEAVE_NONE, CU_TENSOR_MAP_SWIZZLE_128B,
      CU_TENSOR_MAP_L2_PROMOTION_L2_128B, CU_TENSOR_MAP_FLOAT_OOB_FILL_NONE);
}

extern "C" void kernel_launch(void* const* d_in, const int* in_sizes, int n_in,
                              void* d_out, int out_size) {
    void *xq, *wq, *wdq, *hq, *xs, *ws, *wds, *h, *hs;
    cudaGetSymbolAddress(&xq,  g_xq);
    cudaGetSymbolAddress(&xs,  g_xs);
    cudaGetSymbolAddress(&wq,  g_wq);
    cudaGetSymbolAddress(&ws,  g_ws);
    cudaGetSymbolAddress(&wdq, g_wdq);
    cudaGetSymbolAddress(&wds, g_wds);
    cudaGetSymbolAddress(&h,   g_h);
    cudaGetSymbolAddress(&hq,  g_hq);
    cudaGetSymbolAddress(&hs,  g_hs);

    EncFn f = nullptr;
    cudaDriverEntryPointQueryResult qr;
    cudaGetDriverEntryPoint("cuTensorMapEncodeTiled", (void**)&f, cudaEnableDefault, &qr);

    CUtensorMap tA1, tB1, tA2, tB2;
    enc_map(f, &tA1, xq,  HID,  MT);
    enc_map(f, &tB1, wq,  HID,  NGU);
    enc_map(f, &tA2, hq,  INT_, MT);
    enc_map(f, &tB2, wdq, INT_, HID);

    cudaFuncSetAttribute(gemm_dual<true>,  cudaFuncAttributeMaxDynamicSharedMemorySize, 197632);
    cudaFuncSetAttribute(gemm_dual<false>, cudaFuncAttributeMaxDynamicSharedMemorySize, 197632);
    cudaFuncSetAttribute(fwht_quant,       cudaFuncAttributeMaxDynamicSharedMemorySize, 65536);

    quant_rows<4><<<MT,  256>>>((const float*)d_in[0], (uint8_t*)xq,  (float*)xs,  HID);
    quant_rows<4><<<NGU, 256>>>((const float*)d_in[1], (uint8_t*)wq,  (float*)ws,  HID);
    quant_rows<16><<<HID, 256>>>((const float*)d_in[2], (uint8_t*)wdq, (float*)wds, INT_);

    gemm_dual<true><<<dim3(32, 128), 256, 197632>>>(
        tA1, tB1, (const float*)xs, (const float*)ws, (float*)h, HID, INT_);

    fwht_quant<<<MT, 512, 65536>>>((const float*)h, (uint8_t*)hq, (float*)hs);

    gemm_dual<false><<<dim3(32, 16), 256, 197632>>>(
        tA2, tB2, (const float*)hs, (const float*)wds, (float*)d_out, INT_, HID);
}

// round 15
// speedup vs baseline: 1.2415x; 1.1708x over previous
#include <cuda_runtime.h>
#include <cuda.h>
#include <cstdint>
#include <cstddef>

#define HID  4096
#define INT_ 16384
#define MT   4096
#define NGU  32768

__device__ uint8_t g_xq [(size_t)MT  * HID];
__device__ float   g_xs [MT];
__device__ uint8_t g_wq [(size_t)NGU * HID];
__device__ float   g_ws [NGU];
__device__ uint8_t g_wdq[(size_t)HID * INT_];
__device__ float   g_wds[HID];
__device__ float   g_h  [(size_t)MT * INT_];
__device__ uint8_t g_hq [(size_t)MT * INT_];
__device__ float   g_hs [MT];

__device__ __forceinline__ uint32_t smem_u32(const void* p) {
    uint32_t a;
    asm("{ .reg .u64 t; cvta.to.shared.u64 t, %1; cvt.u32.u64 %0, t; }" : "=r"(a) : "l"(p));
    return a;
}
__device__ __forceinline__ uint32_t elect_one() {
    uint32_t p;
    asm volatile("{ .reg .pred p; elect.sync _|p, 0xFFFFFFFF; selp.b32 %0, 1, 0, p; }" : "=r"(p));
    return p;
}
#define MBARRIER_INIT(mb, c) \
    asm volatile("mbarrier.init.shared.b64 [%0], %1;" :: "r"((uint32_t)(mb)), "r"((uint32_t)(c)) : "memory")
#define MBARRIER_EXPECT_TX(mb, n) \
    asm volatile("mbarrier.arrive.expect_tx.shared.b64 _, [%0], %1;" \
                 :: "r"((uint32_t)(mb)), "r"((uint32_t)(n)) : "memory")
#define MBARRIER_ARRIVE(mb) \
    asm volatile("mbarrier.arrive.shared.b64 _, [%0];" :: "r"((uint32_t)(mb)) : "memory")
#define MBARRIER_WAIT(mb, ph) do {                                                    \
    uint32_t _m = (uint32_t)(mb); uint32_t _p = (uint32_t)(ph); uint32_t _d;           \
    asm volatile("{\n\t.reg .pred p;\n\t"                                              \
        "mbarrier.try_wait.parity.acquire.cta.shared::cta.b64 p, [%1], %2;\n\t"        \
        "selp.b32 %0, 1, 0, p;\n\t}" : "=r"(_d) : "r"(_m), "r"(_p) : "memory");        \
    if (!_d) {                                                                         \
        asm volatile("{\n\t.reg .pred P1;\n\t"                                         \
            "WL_%=:\n\t"                                                               \
            "mbarrier.try_wait.parity.acquire.cta.shared::cta.b64 P1, [%0], %1, 0x989680;\n\t" \
            "@P1 bra.uni WD_%=;\n\t"                                                   \
            "bra.uni WL_%=;\n\t"                                                       \
            "WD_%=:\n\t}" :: "r"(_m), "r"(_p) : "memory");                             \
    }                                                                                  \
} while (0)
#define TMA2D(sm, map, cx, cy, mb) \
    asm volatile("cp.async.bulk.tensor.2d.shared::cta.global.tile.mbarrier::complete_tx::bytes " \
                 "[%0], [%1, {%2, %3}], [%4];" \
                 :: "r"((uint32_t)(sm)), "l"(map), "r"((int)(cx)), "r"((int)(cy)), \
                    "r"((uint32_t)(mb)) : "memory")
#define LDS32(r, a) asm volatile("ld.shared.b32 %0, [%1];" : "=r"(r) : "r"(a))
#define IMMA(c, a, b0_, b1_) \
    asm volatile("mma.sync.aligned.m16n8k32.row.col.s32.s8.s8.s32 " \
        "{%0,%1,%2,%3}, {%4,%5,%6,%7}, {%8,%9}, {%0,%1,%2,%3};" \
        : "+r"((c)[0]), "+r"((c)[1]), "+r"((c)[2]), "+r"((c)[3]) \
        : "r"((a)[0]), "r"((a)[1]), "r"((a)[2]), "r"((a)[3]), "r"(b0_), "r"(b1_))

__device__ __forceinline__ float tanh_xla(float x) {
    if (fabsf(x) < 0.0004f) return x;
    float xc = fminf(fmaxf(x, -7.90531110763549805f), 7.90531110763549805f);
    float x2 = xc * xc;
    float p = fmaf(x2, -2.76076847742355e-16f, 2.00018790482477e-13f);
    p = fmaf(x2, p, -8.60467152213735e-11f);
    p = fmaf(x2, p, 5.12229709037114e-08f);
    p = fmaf(x2, p, 1.48572235717979e-05f);
    p = fmaf(x2, p, 6.37261928875436e-04f);
    p = fmaf(x2, p, 4.89352455891786e-03f);
    p = xc * p;
    float q = fmaf(x2, 1.19825839466702e-06f, 1.18534705686654e-04f);
    q = fmaf(x2, q, 2.26843463243900e-03f);
    q = fmaf(x2, q, 4.89352518554385e-03f);
    return __fdiv_rn(p, q);
}
__device__ __forceinline__ float silu_xla(float g, float u) {
    float sig = fmaf(0.5f, tanh_xla(0.5f * g), 0.5f);
    return (g * sig) * u;
}
__device__ __forceinline__ int q_fast(float x, float inv) {
    int qi = __float2int_rn(x * inv);
    return max(-8, min(7, qi));
}
__device__ __forceinline__ uint32_t pack4i(float a, float b, float c, float d, float inv) {
    int q0 = q_fast(a, inv), q1 = q_fast(b, inv);
    int q2 = q_fast(c, inv), q3 = q_fast(d, inv);
    return (uint32_t)(q0 & 255) | ((uint32_t)(q1 & 255) << 8) |
           ((uint32_t)(q2 & 255) << 16) | ((uint32_t)(q3 & 255) << 24);
}
// matches reference-as-compiled: scale = max * RN(1/7)
__device__ __forceinline__ float mk_scale(float mx) {
    return fmaxf(mx * (1.0f / 7.0f), 1e-8f);
}

template <int VPT>
__global__ void __launch_bounds__(256)
quant_rows(const float* __restrict__ X, uint8_t* __restrict__ Q,
           float* __restrict__ S, int K) {
    __shared__ float red[8];
    int row = blockIdx.x, t = threadIdx.x;
    const float4* src = (const float4*)(X + (size_t)row * K);
    float4 v[VPT];
    float mx = 0.f;
#pragma unroll
    for (int i = 0; i < VPT; i++) {
        v[i] = src[t + i * 256];
        mx = fmaxf(mx, fmaxf(fmaxf(fabsf(v[i].x), fabsf(v[i].y)),
                             fmaxf(fabsf(v[i].z), fabsf(v[i].w))));
    }
#pragma unroll
    for (int o = 16; o; o >>= 1) mx = fmaxf(mx, __shfl_xor_sync(~0u, mx, o));
    if ((t & 31) == 0) red[t >> 5] = mx;
    __syncthreads();
    if (t < 32) {
        float m2 = (t < 8) ? red[t] : 0.f;
#pragma unroll
        for (int o = 4; o; o >>= 1) m2 = fmaxf(m2, __shfl_xor_sync(~0u, m2, o));
        if (t == 0) red[0] = m2;
    }
    __syncthreads();
    float s = mk_scale(red[0]);
    float inv = __frcp_rn(s);
    if (t == 0) S[row] = s;
    uint32_t* dst = (uint32_t*)(Q + (size_t)row * K);
#pragma unroll
    for (int i = 0; i < VPT; i++)
        dst[t + i * 256] = pack4i(v[i].x, v[i].y, v[i].z, v[i].w, inv);
}

// dual-tile s8 GEMM: tile0 on IMMA (tensor pipe), tile1 on dp4a (fma pipe).
// Disjoint accumulators -> independent instruction streams.
template <bool SILU>
__global__ void __launch_bounds__(256, 1)
gemm_dual(const __grid_constant__ CUtensorMap tmA,
          const __grid_constant__ CUtensorMap tmB,
          const float* __restrict__ sA, const float* __restrict__ sB,
          float* __restrict__ OUT, int K, int ldo) {
    extern __shared__ uint8_t dynraw[];
    __shared__ __align__(8) uint64_t barr[8];
    __shared__ float sB_sm[2][128];
    __shared__ float sA_sm[128];

    const int tid = threadIdx.x, wid = tid >> 5, lid = tid & 31;
    const int m0 = blockIdx.x * 128;
    const int r0 = SILU ? blockIdx.y * 128 : blockIdx.y * 256;
    const int r1 = SILU ? (INT_ + r0) : (r0 + 128);
    const int c0 = r0;
    const int NC = K >> 7;

    const uint32_t dynb = (smem_u32(dynraw) + 1023) & ~1023u;
    const uint32_t mbF = smem_u32(barr), mbE = mbF + 32;

    if (tid == 0)
        for (int s = 0; s < 4; s++) { MBARRIER_INIT(mbF + 8 * s, 1); MBARRIER_INIT(mbE + 8 * s, 256); }
    if (tid < 128) {
        sB_sm[0][tid] = sB[r0 + tid];
        sB_sm[1][tid] = sB[r1 + tid];
        sA_sm[tid]    = sA[m0 + tid];
    }
    __syncthreads();

    const int g   = lid >> 2;
    const int t4  = (lid & 3) * 4;
    const int t2  = (lid & 3) * 2;
    const int m0w = (wid >> 2) * 64;
    const int n0w = (wid & 3) * 32;

    int acc[2][4][4][4];
#pragma unroll
    for (int a = 0; a < 2; a++)
#pragma unroll
        for (int b = 0; b < 4; b++)
#pragma unroll
            for (int c = 0; c < 4; c++)
#pragma unroll
                for (int d = 0; d < 4; d++) acc[a][b][c][d] = 0;

    const bool prod = (wid == 0) && elect_one();
    auto issue = [&](int nx) {
        uint32_t s = nx & 3;
        if (nx >= 4) MBARRIER_WAIT(mbE + 8 * s, ((nx - 4) >> 2) & 1);
        uint32_t stg = dynb + s * 49152;
        MBARRIER_EXPECT_TX(mbF + 8 * s, 49152);
        TMA2D(stg,         &tmA, nx * 128, m0, mbF + 8 * s);
        TMA2D(stg + 16384, &tmB, nx * 128, r0, mbF + 8 * s);
        TMA2D(stg + 32768, &tmB, nx * 128, r1, mbF + 8 * s);
    };
    if (prod) { issue(0); issue(1); issue(2); }

    for (int cc = 0; cc < NC; cc++) {
        if (prod && cc + 3 < NC) issue(cc + 3);
        uint32_t s = cc & 3;
        MBARRIER_WAIT(mbF + 8 * s, (cc >> 2) & 1);
        uint32_t stg = dynb + s * 49152;
#pragma unroll
        for (int ks = 0; ks < 4; ks++) {
            // ---- tile0 on IMMA ----
            const int kb = ks * 32 + t4;
            uint32_t a[4][4];
#pragma unroll
            for (int mf = 0; mf < 4; mf++) {
                int r = m0w + mf * 16 + g;
                uint32_t rb = stg + r * 128;
                uint32_t sw = (r & 7) << 4;
                LDS32(a[mf][0], rb +        ( kb       ^ sw));
                LDS32(a[mf][1], rb + 1024 + ( kb       ^ sw));
                LDS32(a[mf][2], rb +        ((kb + 16) ^ sw));
                LDS32(a[mf][3], rb + 1024 + ((kb + 16) ^ sw));
            }
#pragma unroll
            for (int nf = 0; nf < 4; nf++) {
                int rn = n0w + nf * 8 + g;
                uint32_t rb = stg + 16384 + rn * 128;
                uint32_t sw = (rn & 7) << 4;
                uint32_t b0, b1;
                LDS32(b0, rb + ( kb       ^ sw));
                LDS32(b1, rb + ((kb + 16) ^ sw));
#pragma unroll
                for (int mf = 0; mf < 4; mf++)
                    IMMA(acc[0][mf][nf], a[mf], b0, b1);
            }
            // ---- tile1 on dp4a (independent accumulators) ----
#pragma unroll
            for (int w = 0; w < 8; w++) {
                const int kb4 = ks * 32 + w * 4;
                uint32_t av[8], bv[8];
#pragma unroll
                for (int mf = 0; mf < 4; mf++)
#pragma unroll
                    for (int h2 = 0; h2 < 2; h2++) {
                        int r = m0w + mf * 16 + g + h2 * 8;
                        LDS32(av[mf * 2 + h2], stg + r * 128 + (kb4 ^ ((r & 7) << 4)));
                    }
#pragma unroll
                for (int nf = 0; nf < 4; nf++)
#pragma unroll
                    for (int c = 0; c < 2; c++) {
                        int rn = n0w + nf * 8 + t2 + c;
                        LDS32(bv[nf * 2 + c],
                              stg + 32768 + rn * 128 + (kb4 ^ ((rn & 7) << 4)));
                    }
#pragma unroll
                for (int mf = 0; mf < 4; mf++)
#pragma unroll
                    for (int nf = 0; nf < 4; nf++) {
                        acc[1][mf][nf][0] = __dp4a((int)av[mf*2],   (int)bv[nf*2],   acc[1][mf][nf][0]);
                        acc[1][mf][nf][1] = __dp4a((int)av[mf*2],   (int)bv[nf*2+1], acc[1][mf][nf][1]);
                        acc[1][mf][nf][2] = __dp4a((int)av[mf*2+1], (int)bv[nf*2],   acc[1][mf][nf][2]);
                        acc[1][mf][nf][3] = __dp4a((int)av[mf*2+1], (int)bv[nf*2+1], acc[1][mf][nf][3]);
                    }
            }
        }
        MBARRIER_ARRIVE(mbE + 8 * s);
    }

    // epilogue (unchanged)
#pragma unroll
    for (int mf = 0; mf < 4; mf++) {
        int rl = m0w + mf * 16 + g;
        float sa0 = sA_sm[rl], sa1 = sA_sm[rl + 8];
        float* o0 = OUT + (size_t)(m0 + rl)     * ldo + c0;
        float* o1 = OUT + (size_t)(m0 + rl + 8) * ldo + c0;
#pragma unroll
        for (int nf = 0; nf < 4; nf++) {
            int cl = n0w + nf * 8 + t2;
            float s00 = sB_sm[0][cl], s01 = sB_sm[0][cl + 1];
            float s10 = sB_sm[1][cl], s11 = sB_sm[1][cl + 1];
            const int* cg = acc[0][mf][nf];
            const int* cu = acc[1][mf][nf];
            if (SILU) {
                float gg[4] = {(float)cg[0] * sa0 * s00, (float)cg[1] * sa0 * s01,
                               (float)cg[2] * sa1 * s00, (float)cg[3] * sa1 * s01};
                float uu[4] = {(float)cu[0] * sa0 * s10, (float)cu[1] * sa0 * s11,
                               (float)cu[2] * sa1 * s10, (float)cu[3] * sa1 * s11};
                float hh[4];
#pragma unroll
                for (int q = 0; q < 4; q++) hh[q] = silu_xla(gg[q], uu[q]);
                *(float2*)(o0 + cl) = make_float2(hh[0], hh[1]);
                *(float2*)(o1 + cl) = make_float2(hh[2], hh[3]);
            } else {
                *(float2*)(o0 + cl)       = make_float2((float)cg[0] * sa0 * s00,
                                                        (float)cg[1] * sa0 * s01);
                *(float2*)(o1 + cl)       = make_float2((float)cg[2] * sa1 * s00,
                                                        (float)cg[3] * sa1 * s01);
                *(float2*)(o0 + 128 + cl) = make_float2((float)cu[0] * sa0 * s10,
                                                        (float)cu[1] * sa0 * s11);
                *(float2*)(o1 + 128 + cl) = make_float2((float)cu[2] * sa1 * s10,
                                                        (float)cu[3] * sa1 * s11);
            }
        }
    }
}

__global__ void __launch_bounds__(512)
fwht_quant(const float* __restrict__ H, uint8_t* __restrict__ Q, float* __restrict__ S) {
    extern __shared__ float sh[];
    __shared__ float red[16];
    int row = blockIdx.x, t = threadIdx.x;
    const float4* src = (const float4*)(H + (size_t)row * INT_);
#pragma unroll
    for (int i = 0; i < 8; i++) {
        float4 v = src[t + i * 512];
        int b = (t + i * 512) * 4;
        sh[b] = v.x; sh[b + 1] = v.y; sh[b + 2] = v.z; sh[b + 3] = v.w;
    }
    __syncthreads();
    for (int hh = 1; hh < INT_; hh <<= 1) {
        for (int idx = t; idx < INT_ / 2; idx += 512) {
            int i = ((idx & ~(hh - 1)) << 1) | (idx & (hh - 1));
            float a = sh[i], b = sh[i + hh];
            sh[i] = a + b;
            sh[i + hh] = a - b;
        }
        __syncthreads();
    }
    float mx = 0.f;
    for (int i = t; i < INT_; i += 512) {
        float v = sh[i] * 0.0078125f;
        sh[i] = v;
        mx = fmaxf(mx, fabsf(v));
    }
#pragma unroll
    for (int o = 16; o; o >>= 1) mx = fmaxf(mx, __shfl_xor_sync(~0u, mx, o));
    if ((t & 31) == 0) red[t >> 5] = mx;
    __syncthreads();
    if (t < 32) {
        float m2 = (t < 16) ? red[t] : 0.f;
#pragma unroll
        for (int o = 8; o; o >>= 1) m2 = fmaxf(m2, __shfl_xor_sync(~0u, m2, o));
        if (t == 0) red[0] = m2;
    }
    __syncthreads();
    float s = mk_scale(red[0]);
    float inv = __frcp_rn(s);
    if (t == 0) S[row] = s;
    uint32_t* dst = (uint32_t*)(Q + (size_t)row * INT_);
    for (int i = t; i < INT_ / 4; i += 512)
        dst[i] = pack4i(sh[4 * i], sh[4 * i + 1], sh[4 * i + 2], sh[4 * i + 3], inv);
}

typedef CUresult (*EncFn)(CUtensorMap*, CUtensorMapDataType, cuuint32_t, void*,
                          const cuuint64_t*, const cuuint64_t*, const cuuint32_t*,
                          const cuuint32_t*, CUtensorMapInterleave, CUtensorMapSwizzle,
                          CUtensorMapL2promotion, CUtensorMapFloatOOBfill);

static void enc_map(EncFn f, CUtensorMap* m, void* p, uint64_t d0, uint64_t d1) {
    cuuint64_t dims[2] = {d0, d1};
    cuuint64_t str[1]  = {d0};
    cuuint32_t box[2]  = {128u, 128u};
    cuuint32_t es[2]   = {1u, 1u};
    f(m, CU_TENSOR_MAP_DATA_TYPE_UINT8, 2, p, dims, str, box, es,
      CU_TENSOR_MAP_INTERLEAVE_NONE, CU_TENSOR_MAP_SWIZZLE_128B,
      CU_TENSOR_MAP_L2_PROMOTION_L2_128B, CU_TENSOR_MAP_FLOAT_OOB_FILL_NONE);
}

extern "C" void kernel_launch(void* const* d_in, const int* in_sizes, int n_in,
                              void* d_out, int out_size) {
    void *xq, *wq, *wdq, *hq, *xs, *ws, *wds, *h, *hs;
    cudaGetSymbolAddress(&xq,  g_xq);
    cudaGetSymbolAddress(&xs,  g_xs);
    cudaGetSymbolAddress(&wq,  g_wq);
    cudaGetSymbolAddress(&ws,  g_ws);
    cudaGetSymbolAddress(&wdq, g_wdq);
    cudaGetSymbolAddress(&wds, g_wds);
    cudaGetSymbolAddress(&h,   g_h);
    cudaGetSymbolAddress(&hq,  g_hq);
    cudaGetSymbolAddress(&hs,  g_hs);

    EncFn f = nullptr;
    cudaDriverEntryPointQueryResult qr;
    cudaGetDriverEntryPoint("cuTensorMapEncodeTiled", (void**)&f, cudaEnableDefault, &qr);

    CUtensorMap tA1, tB1, tA2, tB2;
    enc_map(f, &tA1, xq,  HID,  MT);
    enc_map(f, &tB1, wq,  HID,  NGU);
    enc_map(f, &tA2, hq,  INT_, MT);
    enc_map(f, &tB2, wdq, INT_, HID);

    cudaFuncSetAttribute(gemm_dual<true>,  cudaFuncAttributeMaxDynamicSharedMemorySize, 197632);
    cudaFuncSetAttribute(gemm_dual<false>, cudaFuncAttributeMaxDynamicSharedMemorySize, 197632);
    cudaFuncSetAttribute(fwht_quant,       cudaFuncAttributeMaxDynamicSharedMemorySize, 65536);

    quant_rows<4><<<MT,  256>>>((const float*)d_in[0], (uint8_t*)xq,  (float*)xs,  HID);
    quant_rows<4><<<NGU, 256>>>((const float*)d_in[1], (uint8_t*)wq,  (float*)ws,  HID);
    quant_rows<16><<<HID, 256>>>((const float*)d_in[2], (uint8_t*)wdq, (float*)wds, INT_);

    gemm_dual<true><<<dim3(32, 128), 256, 197632>>>(
        tA1, tB1, (const float*)xs, (const float*)ws, (float*)h, HID, INT_);

    fwht_quant<<<MT, 512, 65536>>>((const float*)h, (uint8_t*)hq, (float*)hs);

    gemm_dual<false><<<dim3(32, 16), 256, 197632>>>(
        tA2, tB2, (const float*)hs, (const float*)wds, (float*)d_out, INT_, HID);
}

// round 16
// speedup vs baseline: 1.3154x; 1.0595x over previous
#include <cuda_runtime.h>
#include <cuda.h>
#include <cstdint>
#include <cstddef>

#define HID  4096
#define INT_ 16384
#define MT   4096
#define NGU  32768

__device__ uint8_t g_xq [(size_t)MT  * HID];
__device__ float   g_xs [MT];
__device__ uint8_t g_wq [(size_t)NGU * HID];
__device__ float   g_ws [NGU];
__device__ uint8_t g_wdq[(size_t)HID * INT_];
__device__ float   g_wds[HID];
__device__ float   g_h  [(size_t)MT * INT_];
__device__ uint8_t g_hq [(size_t)MT * INT_];
__device__ float   g_hs [MT];

__device__ __forceinline__ uint32_t smem_u32(const void* p) {
    uint32_t a;
    asm("{ .reg .u64 t; cvta.to.shared.u64 t, %1; cvt.u32.u64 %0, t; }" : "=r"(a) : "l"(p));
    return a;
}
__device__ __forceinline__ uint32_t elect_one() {
    uint32_t p;
    asm volatile("{ .reg .pred p; elect.sync _|p, 0xFFFFFFFF; selp.b32 %0, 1, 0, p; }" : "=r"(p));
    return p;
}
#define MBARRIER_INIT(mb, c) \
    asm volatile("mbarrier.init.shared.b64 [%0], %1;" :: "r"((uint32_t)(mb)), "r"((uint32_t)(c)) : "memory")
#define MBARRIER_EXPECT_TX(mb, n) \
    asm volatile("mbarrier.arrive.expect_tx.shared.b64 _, [%0], %1;" \
                 :: "r"((uint32_t)(mb)), "r"((uint32_t)(n)) : "memory")
#define MBARRIER_ARRIVE(mb) \
    asm volatile("mbarrier.arrive.shared.b64 _, [%0];" :: "r"((uint32_t)(mb)) : "memory")
#define MBARRIER_WAIT(mb, ph) do {                                                    \
    uint32_t _m = (uint32_t)(mb); uint32_t _p = (uint32_t)(ph); uint32_t _d;           \
    asm volatile("{\n\t.reg .pred p;\n\t"                                              \
        "mbarrier.try_wait.parity.acquire.cta.shared::cta.b64 p, [%1], %2;\n\t"        \
        "selp.b32 %0, 1, 0, p;\n\t}" : "=r"(_d) : "r"(_m), "r"(_p) : "memory");        \
    if (!_d) {                                                                         \
        asm volatile("{\n\t.reg .pred P1;\n\t"                                         \
            "WL_%=:\n\t"                                                               \
            "mbarrier.try_wait.parity.acquire.cta.shared::cta.b64 P1, [%0], %1, 0x989680;\n\t" \
            "@P1 bra.uni WD_%=;\n\t"                                                   \
            "bra.uni WL_%=;\n\t"                                                       \
            "WD_%=:\n\t}" :: "r"(_m), "r"(_p) : "memory");                             \
    }                                                                                  \
} while (0)
#define TMA2D(sm, map, cx, cy, mb) \
    asm volatile("cp.async.bulk.tensor.2d.shared::cta.global.tile.mbarrier::complete_tx::bytes " \
                 "[%0], [%1, {%2, %3}], [%4];" \
                 :: "r"((uint32_t)(sm)), "l"(map), "r"((int)(cx)), "r"((int)(cy)), \
                    "r"((uint32_t)(mb)) : "memory")
#define LDS32(r, a) asm volatile("ld.shared.b32 %0, [%1];" : "=r"(r) : "r"(a))
#define LDS128(r0, r1, r2, r3, a) \
    asm volatile("ld.shared.v4.u32 {%0, %1, %2, %3}, [%4];" \
                 : "=r"(r0), "=r"(r1), "=r"(r2), "=r"(r3) : "r"(a))
#define IMMA(c, a, b0_, b1_) \
    asm volatile("mma.sync.aligned.m16n8k32.row.col.s32.s8.s8.s32 " \
        "{%0,%1,%2,%3}, {%4,%5,%6,%7}, {%8,%9}, {%0,%1,%2,%3};" \
        : "+r"((c)[0]), "+r"((c)[1]), "+r"((c)[2]), "+r"((c)[3]) \
        : "r"((a)[0]), "r"((a)[1]), "r"((a)[2]), "r"((a)[3]), "r"(b0_), "r"(b1_))

__device__ __forceinline__ float tanh_xla(float x) {
    if (fabsf(x) < 0.0004f) return x;
    float xc = fminf(fmaxf(x, -7.90531110763549805f), 7.90531110763549805f);
    float x2 = xc * xc;
    float p = fmaf(x2, -2.76076847742355e-16f, 2.00018790482477e-13f);
    p = fmaf(x2, p, -8.60467152213735e-11f);
    p = fmaf(x2, p, 5.12229709037114e-08f);
    p = fmaf(x2, p, 1.48572235717979e-05f);
    p = fmaf(x2, p, 6.37261928875436e-04f);
    p = fmaf(x2, p, 4.89352455891786e-03f);
    p = xc * p;
    float q = fmaf(x2, 1.19825839466702e-06f, 1.18534705686654e-04f);
    q = fmaf(x2, q, 2.26843463243900e-03f);
    q = fmaf(x2, q, 4.89352518554385e-03f);
    return __fdiv_rn(p, q);
}
__device__ __forceinline__ float silu_xla(float g, float u) {
    float sig = fmaf(0.5f, tanh_xla(0.5f * g), 0.5f);
    return (g * sig) * u;
}
__device__ __forceinline__ int q_fast(float x, float inv) {
    int qi = __float2int_rn(x * inv);
    return max(-8, min(7, qi));
}
__device__ __forceinline__ uint32_t pack4i(float a, float b, float c, float d, float inv) {
    int q0 = q_fast(a, inv), q1 = q_fast(b, inv);
    int q2 = q_fast(c, inv), q3 = q_fast(d, inv);
    return (uint32_t)(q0 & 255) | ((uint32_t)(q1 & 255) << 8) |
           ((uint32_t)(q2 & 255) << 16) | ((uint32_t)(q3 & 255) << 24);
}
// matches reference-as-compiled: scale = max * RN(1/7)
__device__ __forceinline__ float mk_scale(float mx) {
    return fmaxf(mx * (1.0f / 7.0f), 1e-8f);
}

template <int VPT>
__global__ void __launch_bounds__(256)
quant_rows(const float* __restrict__ X, uint8_t* __restrict__ Q,
           float* __restrict__ S, int K) {
    __shared__ float red[8];
    int row = blockIdx.x, t = threadIdx.x;
    const float4* src = (const float4*)(X + (size_t)row * K);
    float4 v[VPT];
    float mx = 0.f;
#pragma unroll
    for (int i = 0; i < VPT; i++) {
        v[i] = src[t + i * 256];
        mx = fmaxf(mx, fmaxf(fmaxf(fabsf(v[i].x), fabsf(v[i].y)),
                             fmaxf(fabsf(v[i].z), fabsf(v[i].w))));
    }
#pragma unroll
    for (int o = 16; o; o >>= 1) mx = fmaxf(mx, __shfl_xor_sync(~0u, mx, o));
    if ((t & 31) == 0) red[t >> 5] = mx;
    __syncthreads();
    if (t < 32) {
        float m2 = (t < 8) ? red[t] : 0.f;
#pragma unroll
        for (int o = 4; o; o >>= 1) m2 = fmaxf(m2, __shfl_xor_sync(~0u, m2, o));
        if (t == 0) red[0] = m2;
    }
    __syncthreads();
    float s = mk_scale(red[0]);
    float inv = __frcp_rn(s);
    if (t == 0) S[row] = s;
    uint32_t* dst = (uint32_t*)(Q + (size_t)row * K);
#pragma unroll
    for (int i = 0; i < VPT; i++)
        dst[t + i * 256] = pack4i(v[i].x, v[i].y, v[i].z, v[i].w, inv);
}

// dual-tile s8 GEMM: tile0 on IMMA (tensor pipe), tile1 on dp4a (fma pipe),
// dp4a operands loaded with ld.shared.v4 (swizzle-contiguous 16B halves).
template <bool SILU>
__global__ void __launch_bounds__(256, 1)
gemm_dual(const __grid_constant__ CUtensorMap tmA,
          const __grid_constant__ CUtensorMap tmB,
          const float* __restrict__ sA, const float* __restrict__ sB,
          float* __restrict__ OUT, int K, int ldo) {
    extern __shared__ uint8_t dynraw[];
    __shared__ __align__(8) uint64_t barr[8];
    __shared__ float sB_sm[2][128];
    __shared__ float sA_sm[128];

    const int tid = threadIdx.x, wid = tid >> 5, lid = tid & 31;
    const int m0 = blockIdx.x * 128;
    const int r0 = SILU ? blockIdx.y * 128 : blockIdx.y * 256;
    const int r1 = SILU ? (INT_ + r0) : (r0 + 128);
    const int c0 = r0;
    const int NC = K >> 7;

    const uint32_t dynb = (smem_u32(dynraw) + 1023) & ~1023u;
    const uint32_t mbF = smem_u32(barr), mbE = mbF + 32;

    if (tid == 0)
        for (int s = 0; s < 4; s++) { MBARRIER_INIT(mbF + 8 * s, 1); MBARRIER_INIT(mbE + 8 * s, 256); }
    if (tid < 128) {
        sB_sm[0][tid] = sB[r0 + tid];
        sB_sm[1][tid] = sB[r1 + tid];
        sA_sm[tid]    = sA[m0 + tid];
    }
    __syncthreads();

    const int g   = lid >> 2;
    const int t4  = (lid & 3) * 4;
    const int t2  = (lid & 3) * 2;
    const int m0w = (wid >> 2) * 64;
    const int n0w = (wid & 3) * 32;

    int acc[2][4][4][4];
#pragma unroll
    for (int a = 0; a < 2; a++)
#pragma unroll
        for (int b = 0; b < 4; b++)
#pragma unroll
            for (int c = 0; c < 4; c++)
#pragma unroll
                for (int d = 0; d < 4; d++) acc[a][b][c][d] = 0;

    const bool prod = (wid == 0) && elect_one();
    auto issue = [&](int nx) {
        uint32_t s = nx & 3;
        if (nx >= 4) MBARRIER_WAIT(mbE + 8 * s, ((nx - 4) >> 2) & 1);
        uint32_t stg = dynb + s * 49152;
        MBARRIER_EXPECT_TX(mbF + 8 * s, 49152);
        TMA2D(stg,         &tmA, nx * 128, m0, mbF + 8 * s);
        TMA2D(stg + 16384, &tmB, nx * 128, r0, mbF + 8 * s);
        TMA2D(stg + 32768, &tmB, nx * 128, r1, mbF + 8 * s);
    };
    if (prod) { issue(0); issue(1); issue(2); }

    for (int cc = 0; cc < NC; cc++) {
        if (prod && cc + 3 < NC) issue(cc + 3);
        uint32_t s = cc & 3;
        MBARRIER_WAIT(mbF + 8 * s, (cc >> 2) & 1);
        uint32_t stg = dynb + s * 49152;
#pragma unroll
        for (int ks = 0; ks < 4; ks++) {
            // ---- tile0 on IMMA ----
            const int kb = ks * 32 + t4;
            {
                uint32_t a[4][4];
#pragma unroll
                for (int mf = 0; mf < 4; mf++) {
                    int r = m0w + mf * 16 + g;
                    uint32_t rb = stg + r * 128;
                    uint32_t sw = (r & 7) << 4;
                    LDS32(a[mf][0], rb +        ( kb       ^ sw));
                    LDS32(a[mf][1], rb + 1024 + ( kb       ^ sw));
                    LDS32(a[mf][2], rb +        ((kb + 16) ^ sw));
                    LDS32(a[mf][3], rb + 1024 + ((kb + 16) ^ sw));
                }
#pragma unroll
                for (int nf = 0; nf < 4; nf++) {
                    int rn = n0w + nf * 8 + g;
                    uint32_t rb = stg + 16384 + rn * 128;
                    uint32_t sw = (rn & 7) << 4;
                    uint32_t b0, b1;
                    LDS32(b0, rb + ( kb       ^ sw));
                    LDS32(b1, rb + ((kb + 16) ^ sw));
#pragma unroll
                    for (int mf = 0; mf < 4; mf++)
                        IMMA(acc[0][mf][nf], a[mf], b0, b1);
                }
            }
            // ---- tile1 on dp4a: two 16B halves, v4 loads (swizzle-contiguous) ----
#pragma unroll
            for (int half = 0; half < 2; half++) {
                const int kb16 = ks * 32 + half * 16;
                uint32_t av[8][4], bv[8][4];
#pragma unroll
                for (int mf = 0; mf < 4; mf++)
#pragma unroll
                    for (int h2 = 0; h2 < 2; h2++) {
                        int r = m0w + mf * 16 + g + h2 * 8;
                        uint32_t ad = stg + r * 128 + (kb16 ^ ((r & 7) << 4));
                        LDS128(av[mf*2+h2][0], av[mf*2+h2][1], av[mf*2+h2][2], av[mf*2+h2][3], ad);
                    }
#pragma unroll
                for (int nf = 0; nf < 4; nf++)
#pragma unroll
                    for (int c = 0; c < 2; c++) {
                        int rn = n0w + nf * 8 + t2 + c;
                        uint32_t bd = stg + 32768 + rn * 128 + (kb16 ^ ((rn & 7) << 4));
                        LDS128(bv[nf*2+c][0], bv[nf*2+c][1], bv[nf*2+c][2], bv[nf*2+c][3], bd);
                    }
#pragma unroll
                for (int w = 0; w < 4; w++)
#pragma unroll
                    for (int mf = 0; mf < 4; mf++)
#pragma unroll
                        for (int nf = 0; nf < 4; nf++) {
                            acc[1][mf][nf][0] = __dp4a((int)av[mf*2][w],   (int)bv[nf*2][w],   acc[1][mf][nf][0]);
                            acc[1][mf][nf][1] = __dp4a((int)av[mf*2][w],   (int)bv[nf*2+1][w], acc[1][mf][nf][1]);
                            acc[1][mf][nf][2] = __dp4a((int)av[mf*2+1][w], (int)bv[nf*2][w],   acc[1][mf][nf][2]);
                            acc[1][mf][nf][3] = __dp4a((int)av[mf*2+1][w], (int)bv[nf*2+1][w], acc[1][mf][nf][3]);
                        }
            }
        }
        MBARRIER_ARRIVE(mbE + 8 * s);
    }

    // epilogue (unchanged)
#pragma unroll
    for (int mf = 0; mf < 4; mf++) {
        int rl = m0w + mf * 16 + g;
        float sa0 = sA_sm[rl], sa1 = sA_sm[rl + 8];
        float* o0 = OUT + (size_t)(m0 + rl)     * ldo + c0;
        float* o1 = OUT + (size_t)(m0 + rl + 8) * ldo + c0;
#pragma unroll
        for (int nf = 0; nf < 4; nf++) {
            int cl = n0w + nf * 8 + t2;
            float s00 = sB_sm[0][cl], s01 = sB_sm[0][cl + 1];
            float s10 = sB_sm[1][cl], s11 = sB_sm[1][cl + 1];
            const int* cg = acc[0][mf][nf];
            const int* cu = acc[1][mf][nf];
            if (SILU) {
                float gg[4] = {(float)cg[0] * sa0 * s00, (float)cg[1] * sa0 * s01,
                               (float)cg[2] * sa1 * s00, (float)cg[3] * sa1 * s01};
                float uu[4] = {(float)cu[0] * sa0 * s10, (float)cu[1] * sa0 * s11,
                               (float)cu[2] * sa1 * s10, (float)cu[3] * sa1 * s11};
                float hh[4];
#pragma unroll
                for (int q = 0; q < 4; q++) hh[q] = silu_xla(gg[q], uu[q]);
                *(float2*)(o0 + cl) = make_float2(hh[0], hh[1]);
                *(float2*)(o1 + cl) = make_float2(hh[2], hh[3]);
            } else {
                *(float2*)(o0 + cl)       = make_float2((float)cg[0] * sa0 * s00,
                                                        (float)cg[1] * sa0 * s01);
                *(float2*)(o1 + cl)       = make_float2((float)cg[2] * sa1 * s00,
                                                        (float)cg[3] * sa1 * s01);
                *(float2*)(o0 + 128 + cl) = make_float2((float)cu[0] * sa0 * s10,
                                                        (float)cu[1] * sa0 * s11);
                *(float2*)(o1 + 128 + cl) = make_float2((float)cu[2] * sa1 * s10,
                                                        (float)cu[3] * sa1 * s11);
            }
        }
    }
}

__global__ void __launch_bounds__(512)
fwht_quant(const float* __restrict__ H, uint8_t* __restrict__ Q, float* __restrict__ S) {
    extern __shared__ float sh[];
    __shared__ float red[16];
    int row = blockIdx.x, t = threadIdx.x;
    const float4* src = (const float4*)(H + (size_t)row * INT_);
#pragma unroll
    for (int i = 0; i < 8; i++) {
        float4 v = src[t + i * 512];
        int b = (t + i * 512) * 4;
        sh[b] = v.x; sh[b + 1] = v.y; sh[b + 2] = v.z; sh[b + 3] = v.w;
    }
    __syncthreads();
    for (int hh = 1; hh < INT_; hh <<= 1) {
        for (int idx = t; idx < INT_ / 2; idx += 512) {
            int i = ((idx & ~(hh - 1)) << 1) | (idx & (hh - 1));
            float a = sh[i], b = sh[i + hh];
            sh[i] = a + b;
            sh[i + hh] = a - b;
        }
        __syncthreads();
    }
    float mx = 0.f;
    for (int i = t; i < INT_; i += 512) {
        float v = sh[i] * 0.0078125f;
        sh[i] = v;
        mx = fmaxf(mx, fabsf(v));
    }
#pragma unroll
    for (int o = 16; o; o >>= 1) mx = fmaxf(mx, __shfl_xor_sync(~0u, mx, o));
    if ((t & 31) == 0) red[t >> 5] = mx;
    __syncthreads();
    if (t < 32) {
        float m2 = (t < 16) ? red[t] : 0.f;
#pragma unroll
        for (int o = 8; o; o >>= 1) m2 = fmaxf(m2, __shfl_xor_sync(~0u, m2, o));
        if (t == 0) red[0] = m2;
    }
    __syncthreads();
    float s = mk_scale(red[0]);
    float inv = __frcp_rn(s);
    if (t == 0) S[row] = s;
    uint32_t* dst = (uint32_t*)(Q + (size_t)row * INT_);
    for (int i = t; i < INT_ / 4; i += 512)
        dst[i] = pack4i(sh[4 * i], sh[4 * i + 1], sh[4 * i + 2], sh[4 * i + 3], inv);
}

typedef CUresult (*EncFn)(CUtensorMap*, CUtensorMapDataType, cuuint32_t, void*,
                          const cuuint64_t*, const cuuint64_t*, const cuuint32_t*,
                          const cuuint32_t*, CUtensorMapInterleave, CUtensorMapSwizzle,
                          CUtensorMapL2promotion, CUtensorMapFloatOOBfill);

static void enc_map(EncFn f, CUtensorMap* m, void* p, uint64_t d0, uint64_t d1) {
    cuuint64_t dims[2] = {d0, d1};
    cuuint64_t str[1]  = {d0};
    cuuint32_t box[2]  = {128u, 128u};
    cuuint32_t es[2]   = {1u, 1u};
    f(m, CU_TENSOR_MAP_DATA_TYPE_UINT8, 2, p, dims, str, box, es,
      CU_TENSOR_MAP_INTERLEAVE_NONE, CU_TENSOR_MAP_SWIZZLE_128B,
      CU_TENSOR_MAP_L2_PROMOTION_L2_128B, CU_TENSOR_MAP_FLOAT_OOB_FILL_NONE);
}

extern "C" void kernel_launch(void* const* d_in, const int* in_sizes, int n_in,
                              void* d_out, int out_size) {
    void *xq, *wq, *wdq, *hq, *xs, *ws, *wds, *h, *hs;
    cudaGetSymbolAddress(&xq,  g_xq);
    cudaGetSymbolAddress(&xs,  g_xs);
    cudaGetSymbolAddress(&wq,  g_wq);
    cudaGetSymbolAddress(&ws,  g_ws);
    cudaGetSymbolAddress(&wdq, g_wdq);
    cudaGetSymbolAddress(&wds, g_wds);
    cudaGetSymbolAddress(&h,   g_h);
    cudaGetSymbolAddress(&hq,  g_hq);
    cudaGetSymbolAddress(&hs,  g_hs);

    EncFn f = nullptr;
    cudaDriverEntryPointQueryResult qr;
    cudaGetDriverEntryPoint("cuTensorMapEncodeTiled", (void**)&f, cudaEnableDefault, &qr);

    CUtensorMap tA1, tB1, tA2, tB2;
    enc_map(f, &tA1, xq,  HID,  MT);
    enc_map(f, &tB1, wq,  HID,  NGU);
    enc_map(f, &tA2, hq,  INT_, MT);
    enc_map(f, &tB2, wdq, INT_, HID);

    cudaFuncSetAttribute(gemm_dual<true>,  cudaFuncAttributeMaxDynamicSharedMemorySize, 197632);
    cudaFuncSetAttribute(gemm_dual<false>, cudaFuncAttributeMaxDynamicSharedMemorySize, 197632);
    cudaFuncSetAttribute(fwht_quant,       cudaFuncAttributeMaxDynamicSharedMemorySize, 65536);

    quant_rows<4><<<MT,  256>>>((const float*)d_in[0], (uint8_t*)xq,  (float*)xs,  HID);
    quant_rows<4><<<NGU, 256>>>((const float*)d_in[1], (uint8_t*)wq,  (float*)ws,  HID);
    quant_rows<16><<<HID, 256>>>((const float*)d_in[2], (uint8_t*)wdq, (float*)wds, INT_);

    gemm_dual<true><<<dim3(32, 128), 256, 197632>>>(
        tA1, tB1, (const float*)xs, (const float*)ws, (float*)h, HID, INT_);

    fwht_quant<<<MT, 512, 65536>>>((const float*)h, (uint8_t*)hq, (float*)hs);

    gemm_dual<false><<<dim3(32, 16), 256, 197632>>>(
        tA2, tB2, (const float*)hs, (const float*)wds, (float*)d_out, INT_, HID);
}